// round 14
// baseline (speedup 1.0000x reference)
#include <cuda_runtime.h>
#include <cuda_fp16.h>
#include <mma.h>
#include <math.h>
#include <stdint.h>

using namespace nvcuda;

#define NMAX   100000
#define EMAX   1600000
#define IN_F   256
#define HID    128

// ---------------- device scratch (static; no allocations allowed) -------------
// tgt_hl stored fp16 (halves agg gather traffic). Padded by 128 rows: boundary
// GEMM tile stores unguarded into the pad.
__device__ __align__(16) __half g_tgt_hl[(size_t)(NMAX + 128) * HID];
__device__ __align__(16) float g_sscore[NMAX];
__device__ __align__(16) float g_tscore[NMAX];
__device__ __align__(16) unsigned long long g_srec[EMAX];   // packed (ex, ti)
__device__ int g_deg[NMAX];
__device__ int g_base[NMAX];
__device__ int g_cursor[NMAX];
__device__ int g_bsum[128];
__device__ __align__(16) float g_wsproj[IN_F];
__device__ __align__(16) float g_wtproj[IN_F];
__device__ __align__(16) __half g_Wh[HID * IN_F];   // fp16 W (rounded)
__device__ float g_cs;
__device__ float g_ct;
__device__ int   g_idx64;

// ---------------- edge index accessor ------------------------------------------
__device__ __forceinline__ int edge_at(const void* e, int is64, long long pos) {
    if (is64) return (int)((const long long*)e)[pos];
    return ((const int*)e)[pos];
}

// ---------------- fused setup: detect + proj + W fp16 + zero deg ----------------
__global__ void setup_kernel(const float* __restrict__ W,
                             const float* __restrict__ b_lin,
                             const float* __restrict__ att_w,
                             const float* __restrict__ att_b,
                             const int* __restrict__ edges_i32, int nsrc) {
    int b = blockIdx.x, tid = threadIdx.x;
    if (b == 0) {
        float s = 0.f, t = 0.f;
#pragma unroll 8
        for (int h = 0; h < HID; ++h) {
            float w = W[h * IN_F + tid];
            s += w * att_w[h];
            t += w * att_w[HID + h];
        }
        g_wsproj[tid] = s;
        g_wtproj[tid] = t;
        if (tid == 0) {
            float cs = 0.f, ct = 0.f;
            for (int h = 0; h < HID; ++h) {
                cs += b_lin[h] * att_w[h];
                ct += b_lin[h] * att_w[HID + h];
            }
            g_cs = cs;
            g_ct = ct + att_b[0];
        }
        __shared__ int sflag;
        if (tid == 0) sflag = 0;
        __syncthreads();
        if (tid < 128 && edges_i32[2 * tid + 1] != 0) sflag = 1;
        __syncthreads();
        if (tid == 0) g_idx64 = (sflag == 0) ? 1 : 0;
    } else if (b <= 128) {
        int i = (b - 1) * 256 + tid;       // 32768 W elements
        g_Wh[i] = __float2half_rn(W[i]);
    } else {
        int i = (b - 129) * 256 + tid;
        if (i < nsrc) g_deg[i] = 0;
    }
}

// ---------------- source scores (warp per node) ----------------------------------
__global__ void score_kernel(const float* __restrict__ src, int nsrc) {
    int gtid = blockIdx.x * blockDim.x + threadIdx.x;
    int wid = gtid >> 5;
    int lane = gtid & 31;
    if (wid >= nsrc) return;
    const float* row = src + (size_t)wid * IN_F;

    float4 a = ((const float4*)row)[lane];
    float4 b = ((const float4*)row)[lane + 32];
    float4 pa = ((const float4*)g_wsproj)[lane];
    float4 pb = ((const float4*)g_wsproj)[lane + 32];
    float d = a.x * pa.x + a.y * pa.y + a.z * pa.z + a.w * pa.w
            + b.x * pb.x + b.y * pb.y + b.z * pb.z + b.w * pb.w;
#pragma unroll
    for (int o = 16; o; o >>= 1) d += __shfl_down_sync(0xFFFFFFFFu, d, o);
    if (lane == 0) g_sscore[wid] = d + g_cs;
}

// ================= wmma fp16 GEMM + fused t_score ==============================
// g_tgt_hl[M,128] = fp16( A16 @ W16^T ).  BM=64, BN=128, 256 threads (8 warps,
// warp tile 32x32), 3 CTAs/SM target for latency hiding.
#define LDT 40   // padded fp16 row pitch (80 B)

__global__ void __launch_bounds__(256, 3)
mma_gemm_kernel(const float* __restrict__ A, int M) {
    __shared__ __align__(16) char smem_raw[18944];
    __half* sA = (__half*)smem_raw;                   // 64*40*2  = 5120 B
    __half* sW = (__half*)(smem_raw + 5120);          // 128*40*2 = 10240 B

    int tid = threadIdx.x;
    int warp = tid >> 5;
    int lane = tid & 31;
    int wm = warp & 1;        // 2 warp-rows of 32
    int wn = warp >> 1;       // 4 warp-cols of 32
    int row0 = blockIdx.x * 64;

    int rq[2], cq[2], gq[2];
#pragma unroll
    for (int q = 0; q < 2; ++q) {
        int idx = tid + q * 256;          // 0..511
        rq[q] = idx >> 3;                 // 0..63
        cq[q] = (idx & 7) * 4;            // 0..28
        gq[q] = row0 + rq[q];
    }
    int wrq[2], wcq[2];
#pragma unroll
    for (int q = 0; q < 2; ++q) {
        int idx = tid + q * 256;
        wrq[q] = idx >> 2;                // 0..127
        wcq[q] = (idx & 3) * 8;           // 0,8,16,24
    }

    wmma::fragment<wmma::accumulator, 16, 16, 16, float> acc[2][2];
#pragma unroll
    for (int i = 0; i < 2; ++i)
#pragma unroll
        for (int j = 0; j < 2; ++j) wmma::fill_fragment(acc[i][j], 0.f);

    float tsc[2] = {0.f, 0.f};
    float4 pva[2];
    uint4 pw[2];

#pragma unroll
    for (int q = 0; q < 2; ++q) {
        pva[q] = make_float4(0.f, 0.f, 0.f, 0.f);
        if (gq[q] < M) pva[q] = *(const float4*)(A + (size_t)gq[q] * IN_F + cq[q]);
        pw[q] = *(const uint4*)&g_Wh[wrq[q] * IN_F + wcq[q]];
    }

    for (int k0 = 0; k0 < IN_F; k0 += 32) {
#pragma unroll
        for (int q = 0; q < 2; ++q) {
            *(uint4*)&sW[wrq[q] * LDT + wcq[q]] = pw[q];
            float4 v = pva[q];
            int c4 = cq[q];
            tsc[q] += v.x * g_wtproj[k0 + c4]     + v.y * g_wtproj[k0 + c4 + 1]
                    + v.z * g_wtproj[k0 + c4 + 2] + v.w * g_wtproj[k0 + c4 + 3];
            __half2 h01 = __floats2half2_rn(v.x, v.y);
            __half2 h23 = __floats2half2_rn(v.z, v.w);
            *(uint2*)&sA[rq[q] * LDT + c4] =
                make_uint2(*(uint32_t*)&h01, *(uint32_t*)&h23);
        }
        __syncthreads();

        int kn = k0 + 32;
        if (kn < IN_F) {
#pragma unroll
            for (int q = 0; q < 2; ++q) {
                pva[q] = make_float4(0.f, 0.f, 0.f, 0.f);
                if (gq[q] < M)
                    pva[q] = *(const float4*)(A + (size_t)gq[q] * IN_F + kn + cq[q]);
                pw[q] = *(const uint4*)&g_Wh[wrq[q] * IN_F + kn + wcq[q]];
            }
        }

#pragma unroll
        for (int kf = 0; kf < 2; ++kf) {
            wmma::fragment<wmma::matrix_a, 16, 16, 16, __half,
                           wmma::row_major> af[2];
            wmma::fragment<wmma::matrix_b, 16, 16, 16, __half,
                           wmma::col_major> bf[2];
#pragma unroll
            for (int i = 0; i < 2; ++i)
                wmma::load_matrix_sync(af[i],
                    sA + (wm * 32 + i * 16) * LDT + kf * 16, LDT);
#pragma unroll
            for (int j = 0; j < 2; ++j)
                wmma::load_matrix_sync(bf[j],
                    sW + (wn * 32 + j * 16) * LDT + kf * 16, LDT);
#pragma unroll
            for (int i = 0; i < 2; ++i)
#pragma unroll
                for (int j = 0; j < 2; ++j)
                    wmma::mma_sync(acc[i][j], af[i], bf[j], acc[i][j]);
        }
        __syncthreads();
    }

    // t_score reduction: 8 consecutive lanes share one row
#pragma unroll
    for (int q = 0; q < 2; ++q) {
        float d = tsc[q];
        d += __shfl_down_sync(0xFFFFFFFFu, d, 4, 8);
        d += __shfl_down_sync(0xFFFFFFFFu, d, 2, 8);
        d += __shfl_down_sync(0xFFFFFFFFu, d, 1, 8);
        if ((tid & 7) == 0 && gq[q] < M) g_tscore[gq[q]] = d + g_ct;
    }

    // epilogue: acc -> per-warp smem stage -> fp16 global (pad covers overrun)
    float* wscr = (float*)smem_raw + warp * (16 * 36);
#pragma unroll
    for (int i = 0; i < 2; ++i) {
        __syncwarp();
        wmma::store_matrix_sync(wscr, acc[i][0], 36, wmma::mem_row_major);
        wmma::store_matrix_sync(wscr + 16, acc[i][1], 36, wmma::mem_row_major);
        __syncwarp();
        int row = lane & 15, seg = lane >> 4;
        const float* sp = wscr + row * 36 + seg * 16;
        __half2 h[8];
#pragma unroll
        for (int q = 0; q < 8; ++q)
            h[q] = __floats2half2_rn(sp[2 * q], sp[2 * q + 1]);
        size_t grow = (size_t)row0 + wm * 32 + i * 16 + row;
        __half* gp = g_tgt_hl + grow * HID + wn * 32 + seg * 16;
        *(uint4*)gp = *(uint4*)&h[0];
        *(uint4*)(gp + 8) = *(uint4*)&h[4];
    }
}

// ---------------- degree histogram (reads si only) -------------------------------
__global__ void hist_kernel(const void* __restrict__ edges, int E) {
    int i = blockIdx.x * blockDim.x + threadIdx.x;
    if (i >= E) return;
    int si = edge_at(edges, g_idx64, i);
    atomicAdd(&g_deg[si], 1);
}

// ---------------- exclusive scan of degrees --------------------------------------
__global__ void scan1_kernel(int n) {
    __shared__ int s[1024];
    int i = blockIdx.x * 1024 + threadIdx.x;
    int v = (i < n) ? g_deg[i] : 0;
    s[threadIdx.x] = v;
    __syncthreads();
#pragma unroll
    for (int o = 1; o < 1024; o <<= 1) {
        int t = (threadIdx.x >= o) ? s[threadIdx.x - o] : 0;
        __syncthreads();
        s[threadIdx.x] += t;
        __syncthreads();
    }
    if (i < n) g_base[i] = s[threadIdx.x] - v;
    if (threadIdx.x == 1023) g_bsum[blockIdx.x] = s[1023];
}
__global__ void scan2_kernel(int nb) {
    __shared__ int s[128];
    int v = (threadIdx.x < nb) ? g_bsum[threadIdx.x] : 0;
    s[threadIdx.x] = v;
    __syncthreads();
#pragma unroll
    for (int o = 1; o < 128; o <<= 1) {
        int t = (threadIdx.x >= o) ? s[threadIdx.x - o] : 0;
        __syncthreads();
        s[threadIdx.x] += t;
        __syncthreads();
    }
    if (threadIdx.x < nb) g_bsum[threadIdx.x] = s[threadIdx.x] - v;
}
__global__ void scan3_kernel(int n) {
    int i = blockIdx.x * blockDim.x + threadIdx.x;
    if (i < n) {
        int b = g_base[i] + g_bsum[i >> 10];
        g_base[i] = b;
        g_cursor[i] = b;
    }
}

// ---------------- scatter: compute ex and write (ex, ti) sorted by si ------------
// e in [-1,1] (tanh): segment-max cancels mathematically in the softmax.
__global__ void scatter_kernel(const void* __restrict__ edges, int E) {
    int i = blockIdx.x * blockDim.x + threadIdx.x;
    if (i >= E) return;
    int is64 = g_idx64;
    int si = edge_at(edges, is64, i);
    int ti = edge_at(edges, is64, (long long)E + i);
    float e = tanhf(g_sscore[si] + g_tscore[ti]);
    float ex = __expf(e);
    int pos = atomicAdd(&g_cursor[si], 1);
    g_srec[pos] = ((unsigned long long)(unsigned)__float_as_int(ex) << 32)
                | (unsigned)ti;
}

// ---------------- aggregate (warp per source node, fp16 rows) ---------------------
// out = (sum ex*v)/(sum ex) + b_lin + bias   (deg>0; else bias only)
__global__ void agg_kernel(float* __restrict__ out,
                           const float* __restrict__ bias,
                           const float* __restrict__ b_lin, int nsrc) {
    int wid = (blockIdx.x * blockDim.x + threadIdx.x) >> 5;
    int lane = threadIdx.x & 31;
    if (wid >= nsrc) return;
    int start = g_base[wid];
    int deg   = g_deg[wid];

    float4 res = ((const float4*)bias)[lane];
    if (deg > 0) {
        float4 acc = make_float4(0.f, 0.f, 0.f, 0.f);
        float denom = 0.f;
        for (int p = start; p < start + deg; ++p) {
            unsigned long long r = g_srec[p];
            int ti = (int)(unsigned)(r & 0xffffffffu);
            float ex = __int_as_float((int)(r >> 32));
            denom += ex;
            uint2 pk = ((const uint2*)(g_tgt_hl + (size_t)ti * HID))[lane];
            float2 f0 = __half22float2(*(__half2*)&pk.x);
            float2 f1 = __half22float2(*(__half2*)&pk.y);
            acc.x += ex * f0.x; acc.y += ex * f0.y;
            acc.z += ex * f1.x; acc.w += ex * f1.y;
        }
        float inv = 1.f / denom;
        float4 bl = ((const float4*)b_lin)[lane];
        res.x += bl.x + acc.x * inv; res.y += bl.y + acc.y * inv;
        res.z += bl.z + acc.z * inv; res.w += bl.w + acc.w * inv;
    }
    ((float4*)(out + (size_t)wid * HID))[lane] = res;
}

// ---------------- launch: parallel graph branches ----------------------------------
// Branch A (default stream): gemm.  Branch B (side stream): hist, scans, score.
// Fork/join via events so the captured graph runs A and B concurrently.
extern "C" void kernel_launch(void* const* d_in, const int* in_sizes, int n_in,
                              void* d_out, int out_size) {
    const float* source_h   = (const float*)d_in[0];
    const float* target_h   = (const float*)d_in[1];
    const void*  edges      = d_in[2];
    const float* W          = (const float*)d_in[3];
    const float* b_lin      = (const float*)d_in[4];
    const float* att_w      = (const float*)d_in[5];
    const float* att_b      = (const float*)d_in[6];
    const float* bias       = (const float*)d_in[7];

    int nsrc = in_sizes[0] / IN_F;
    int ntgt = in_sizes[1] / IN_F;
    int E    = in_sizes[2] / 2;
    float* out = (float*)d_out;
    int nb = (nsrc + 1023) / 1024;

    static cudaStream_t s_side = nullptr;
    static cudaEvent_t ev_fork = nullptr, ev_join = nullptr;
    if (s_side == nullptr) {
        cudaStreamCreateWithFlags(&s_side, cudaStreamNonBlocking);
        cudaEventCreateWithFlags(&ev_fork, cudaEventDisableTiming);
        cudaEventCreateWithFlags(&ev_join, cudaEventDisableTiming);
    }

    setup_kernel<<<129 + (nsrc + 255) / 256, 256>>>(
        W, b_lin, att_w, att_b, (const int*)edges, nsrc);

    // fork
    cudaEventRecord(ev_fork, 0);
    cudaStreamWaitEvent(s_side, ev_fork, 0);

    // Branch B (side stream): DRAM-bound edge/score work
    hist_kernel<<<(E + 255) / 256, 256, 0, s_side>>>(edges, E);
    score_kernel<<<(int)(((long long)nsrc * 32 + 255) / 256), 256, 0, s_side>>>(
        source_h, nsrc);
    scan1_kernel<<<nb, 1024, 0, s_side>>>(nsrc);
    scan2_kernel<<<1, 128, 0, s_side>>>(nb);
    scan3_kernel<<<(nsrc + 255) / 256, 256, 0, s_side>>>(nsrc);

    // Branch A (default stream): tensor GEMM + t_score
    mma_gemm_kernel<<<(ntgt + 63) / 64, 256>>>(target_h, ntgt);

    // join
    cudaEventRecord(ev_join, s_side);
    cudaStreamWaitEvent(0, ev_join, 0);

    scatter_kernel<<<(E + 255) / 256, 256>>>(edges, E);
    agg_kernel<<<(int)(((long long)nsrc * 32 + 255) / 256), 256>>>(
        out, bias, b_lin, nsrc);
}

// round 15
// speedup vs baseline: 1.2625x; 1.2625x over previous
#include <cuda_runtime.h>
#include <cuda_fp16.h>
#include <mma.h>
#include <math.h>
#include <stdint.h>

using namespace nvcuda;

#define NMAX   100000
#define EMAX   1600000
#define IN_F   256
#define HID    128

// ---------------- device scratch (static; no allocations allowed) -------------
// tgt_hl stored fp16 (halves agg gather traffic). Padded by 128 rows: boundary
// GEMM tile stores unguarded into the pad.
__device__ __align__(16) __half g_tgt_hl[(size_t)(NMAX + 128) * HID];
__device__ __align__(16) float g_sscore[NMAX];
__device__ __align__(16) float g_tscore[NMAX];
__device__ __align__(16) unsigned long long g_srec[EMAX];   // packed (ex, ti)
__device__ int g_deg[NMAX];
__device__ int g_base[NMAX];
__device__ int g_cursor[NMAX];
__device__ int g_bsum[128];
__device__ __align__(16) float g_wsproj[IN_F];
__device__ __align__(16) float g_wtproj[IN_F];
__device__ __align__(16) __half g_Wh[HID * IN_F];   // fp16 W (rounded)
__device__ float g_cs;
__device__ float g_ct;
__device__ int   g_idx64;

// ---------------- edge index accessor ------------------------------------------
__device__ __forceinline__ int edge_at(const void* e, int is64, long long pos) {
    if (is64) return (int)((const long long*)e)[pos];
    return ((const int*)e)[pos];
}

// ---------------- fused setup: detect + proj + W fp16 + zero deg ----------------
__global__ void setup_kernel(const float* __restrict__ W,
                             const float* __restrict__ b_lin,
                             const float* __restrict__ att_w,
                             const float* __restrict__ att_b,
                             const int* __restrict__ edges_i32, int nsrc) {
    int b = blockIdx.x, tid = threadIdx.x;
    if (b == 0) {
        float s = 0.f, t = 0.f;
#pragma unroll 8
        for (int h = 0; h < HID; ++h) {
            float w = W[h * IN_F + tid];
            s += w * att_w[h];
            t += w * att_w[HID + h];
        }
        g_wsproj[tid] = s;
        g_wtproj[tid] = t;
        if (tid == 0) {
            float cs = 0.f, ct = 0.f;
            for (int h = 0; h < HID; ++h) {
                cs += b_lin[h] * att_w[h];
                ct += b_lin[h] * att_w[HID + h];
            }
            g_cs = cs;
            g_ct = ct + att_b[0];
        }
        __shared__ int sflag;
        if (tid == 0) sflag = 0;
        __syncthreads();
        if (tid < 128 && edges_i32[2 * tid + 1] != 0) sflag = 1;
        __syncthreads();
        if (tid == 0) g_idx64 = (sflag == 0) ? 1 : 0;
    } else if (b <= 128) {
        int i = (b - 1) * 256 + tid;       // 32768 W elements
        g_Wh[i] = __float2half_rn(W[i]);
    } else {
        int i = (b - 129) * 256 + tid;
        if (i < nsrc) g_deg[i] = 0;
    }
}

// ---------------- source scores (warp per node) ----------------------------------
__global__ void score_kernel(const float* __restrict__ src, int nsrc) {
    int gtid = blockIdx.x * blockDim.x + threadIdx.x;
    int wid = gtid >> 5;
    int lane = gtid & 31;
    if (wid >= nsrc) return;
    const float* row = src + (size_t)wid * IN_F;

    float4 a = ((const float4*)row)[lane];
    float4 b = ((const float4*)row)[lane + 32];
    float4 pa = ((const float4*)g_wsproj)[lane];
    float4 pb = ((const float4*)g_wsproj)[lane + 32];
    float d = a.x * pa.x + a.y * pa.y + a.z * pa.z + a.w * pa.w
            + b.x * pb.x + b.y * pb.y + b.z * pb.z + b.w * pb.w;
#pragma unroll
    for (int o = 16; o; o >>= 1) d += __shfl_down_sync(0xFFFFFFFFu, d, o);
    if (lane == 0) g_sscore[wid] = d + g_cs;
}

// ================= wmma fp16 GEMM + fused t_score ==============================
// g_tgt_hl[M,128] = fp16( A16 @ W16^T ).  BM=64, BN=128, 256 threads (8 warps,
// warp tile 32x32), 3 CTAs/SM target for latency hiding.
#define LDT 40   // padded fp16 row pitch (80 B)

__global__ void __launch_bounds__(256, 3)
mma_gemm_kernel(const float* __restrict__ A, int M) {
    __shared__ __align__(16) char smem_raw[18944];
    __half* sA = (__half*)smem_raw;                   // 64*40*2  = 5120 B
    __half* sW = (__half*)(smem_raw + 5120);          // 128*40*2 = 10240 B

    int tid = threadIdx.x;
    int warp = tid >> 5;
    int lane = tid & 31;
    int wm = warp & 1;        // 2 warp-rows of 32
    int wn = warp >> 1;       // 4 warp-cols of 32
    int row0 = blockIdx.x * 64;

    int rq[2], cq[2], gq[2];
#pragma unroll
    for (int q = 0; q < 2; ++q) {
        int idx = tid + q * 256;          // 0..511
        rq[q] = idx >> 3;                 // 0..63
        cq[q] = (idx & 7) * 4;            // 0..28
        gq[q] = row0 + rq[q];
    }
    int wrq[2], wcq[2];
#pragma unroll
    for (int q = 0; q < 2; ++q) {
        int idx = tid + q * 256;
        wrq[q] = idx >> 2;                // 0..127
        wcq[q] = (idx & 3) * 8;           // 0,8,16,24
    }

    wmma::fragment<wmma::accumulator, 16, 16, 16, float> acc[2][2];
#pragma unroll
    for (int i = 0; i < 2; ++i)
#pragma unroll
        for (int j = 0; j < 2; ++j) wmma::fill_fragment(acc[i][j], 0.f);

    float tsc[2] = {0.f, 0.f};
    float4 pva[2];
    uint4 pw[2];

#pragma unroll
    for (int q = 0; q < 2; ++q) {
        pva[q] = make_float4(0.f, 0.f, 0.f, 0.f);
        if (gq[q] < M) pva[q] = *(const float4*)(A + (size_t)gq[q] * IN_F + cq[q]);
        pw[q] = *(const uint4*)&g_Wh[wrq[q] * IN_F + wcq[q]];
    }

    for (int k0 = 0; k0 < IN_F; k0 += 32) {
#pragma unroll
        for (int q = 0; q < 2; ++q) {
            *(uint4*)&sW[wrq[q] * LDT + wcq[q]] = pw[q];
            float4 v = pva[q];
            int c4 = cq[q];
            tsc[q] += v.x * g_wtproj[k0 + c4]     + v.y * g_wtproj[k0 + c4 + 1]
                    + v.z * g_wtproj[k0 + c4 + 2] + v.w * g_wtproj[k0 + c4 + 3];
            __half2 h01 = __floats2half2_rn(v.x, v.y);
            __half2 h23 = __floats2half2_rn(v.z, v.w);
            *(uint2*)&sA[rq[q] * LDT + c4] =
                make_uint2(*(uint32_t*)&h01, *(uint32_t*)&h23);
        }
        __syncthreads();

        int kn = k0 + 32;
        if (kn < IN_F) {
#pragma unroll
            for (int q = 0; q < 2; ++q) {
                pva[q] = make_float4(0.f, 0.f, 0.f, 0.f);
                if (gq[q] < M)
                    pva[q] = *(const float4*)(A + (size_t)gq[q] * IN_F + kn + cq[q]);
                pw[q] = *(const uint4*)&g_Wh[wrq[q] * IN_F + kn + wcq[q]];
            }
        }

#pragma unroll
        for (int kf = 0; kf < 2; ++kf) {
            wmma::fragment<wmma::matrix_a, 16, 16, 16, __half,
                           wmma::row_major> af[2];
            wmma::fragment<wmma::matrix_b, 16, 16, 16, __half,
                           wmma::col_major> bf[2];
#pragma unroll
            for (int i = 0; i < 2; ++i)
                wmma::load_matrix_sync(af[i],
                    sA + (wm * 32 + i * 16) * LDT + kf * 16, LDT);
#pragma unroll
            for (int j = 0; j < 2; ++j)
                wmma::load_matrix_sync(bf[j],
                    sW + (wn * 32 + j * 16) * LDT + kf * 16, LDT);
#pragma unroll
            for (int i = 0; i < 2; ++i)
#pragma unroll
                for (int j = 0; j < 2; ++j)
                    wmma::mma_sync(acc[i][j], af[i], bf[j], acc[i][j]);
        }
        __syncthreads();
    }

    // t_score reduction: 8 consecutive lanes share one row
#pragma unroll
    for (int q = 0; q < 2; ++q) {
        float d = tsc[q];
        d += __shfl_down_sync(0xFFFFFFFFu, d, 4, 8);
        d += __shfl_down_sync(0xFFFFFFFFu, d, 2, 8);
        d += __shfl_down_sync(0xFFFFFFFFu, d, 1, 8);
        if ((tid & 7) == 0 && gq[q] < M) g_tscore[gq[q]] = d + g_ct;
    }

    // epilogue: acc -> per-warp smem stage -> fp16 global (pad covers overrun)
    float* wscr = (float*)smem_raw + warp * (16 * 36);
#pragma unroll
    for (int i = 0; i < 2; ++i) {
        __syncwarp();
        wmma::store_matrix_sync(wscr, acc[i][0], 36, wmma::mem_row_major);
        wmma::store_matrix_sync(wscr + 16, acc[i][1], 36, wmma::mem_row_major);
        __syncwarp();
        int row = lane & 15, seg = lane >> 4;
        const float* sp = wscr + row * 36 + seg * 16;
        __half2 h[8];
#pragma unroll
        for (int q = 0; q < 8; ++q)
            h[q] = __floats2half2_rn(sp[2 * q], sp[2 * q + 1]);
        size_t grow = (size_t)row0 + wm * 32 + i * 16 + row;
        __half* gp = g_tgt_hl + grow * HID + wn * 32 + seg * 16;
        *(uint4*)gp = *(uint4*)&h[0];
        *(uint4*)(gp + 8) = *(uint4*)&h[4];
    }
}

// ---------------- degree histogram (reads si only) -------------------------------
__global__ void hist_kernel(const void* __restrict__ edges, int E) {
    int i = blockIdx.x * blockDim.x + threadIdx.x;
    if (i >= E) return;
    int si = edge_at(edges, g_idx64, i);
    atomicAdd(&g_deg[si], 1);
}

// ---------------- exclusive scan of degrees (2 kernels) ---------------------------
__global__ void scan1_kernel(int n) {
    __shared__ int s[1024];
    int i = blockIdx.x * 1024 + threadIdx.x;
    int v = (i < n) ? g_deg[i] : 0;
    s[threadIdx.x] = v;
    __syncthreads();
#pragma unroll
    for (int o = 1; o < 1024; o <<= 1) {
        int t = (threadIdx.x >= o) ? s[threadIdx.x - o] : 0;
        __syncthreads();
        s[threadIdx.x] += t;
        __syncthreads();
    }
    if (i < n) g_base[i] = s[threadIdx.x] - v;
    if (threadIdx.x == 1023) g_bsum[blockIdx.x] = s[1023];
}
// scan3 also absorbs scan2: every block redundantly prefix-scans the <=128
// block sums in smem; a 256-thread block covers one (i>>10) group only.
__global__ void scan3_kernel(int n, int nb) {
    __shared__ int s[128];
    int t = threadIdx.x;
    if (t < 128) s[t] = (t < nb) ? g_bsum[t] : 0;
    __syncthreads();
#pragma unroll
    for (int o = 1; o < 128; o <<= 1) {
        int v = (t < 128 && t >= o) ? s[t - o] : 0;
        __syncthreads();
        if (t < 128) s[t] += v;
        __syncthreads();
    }
    int grp = blockIdx.x >> 2;               // constant i>>10 within this block
    int add = (grp == 0) ? 0 : s[grp - 1];   // exclusive prefix
    int i = blockIdx.x * 256 + t;
    if (i < n) {
        int b = g_base[i] + add;
        g_base[i] = b;
        g_cursor[i] = b;
    }
}

// ---------------- scatter: compute ex and write (ex, ti) sorted by si ------------
// e in [-1,1] (tanh): segment-max cancels mathematically in the softmax.
__global__ void scatter_kernel(const void* __restrict__ edges, int E) {
    int i = blockIdx.x * blockDim.x + threadIdx.x;
    if (i >= E) return;
    int is64 = g_idx64;
    int si = edge_at(edges, is64, i);
    int ti = edge_at(edges, is64, (long long)E + i);
    float e = tanhf(g_sscore[si] + g_tscore[ti]);
    float ex = __expf(e);
    int pos = atomicAdd(&g_cursor[si], 1);
    g_srec[pos] = ((unsigned long long)(unsigned)__float_as_int(ex) << 32)
                | (unsigned)ti;
}

// ---------------- aggregate (warp per source node, fp16 rows, 2x unroll) ----------
// out = (sum ex*v)/(sum ex) + b_lin + bias   (deg>0; else bias only)
__global__ void agg_kernel(float* __restrict__ out,
                           const float* __restrict__ bias,
                           const float* __restrict__ b_lin, int nsrc) {
    int wid = (blockIdx.x * blockDim.x + threadIdx.x) >> 5;
    int lane = threadIdx.x & 31;
    if (wid >= nsrc) return;
    int start = g_base[wid];
    int deg   = g_deg[wid];
    int end   = start + deg;

    float4 res = ((const float4*)bias)[lane];
    if (deg > 0) {
        float4 acc = make_float4(0.f, 0.f, 0.f, 0.f);
        float denom = 0.f;
        int p = start;
        for (; p + 2 <= end; p += 2) {
            unsigned long long r0 = g_srec[p];
            unsigned long long r1 = g_srec[p + 1];
            int ti0 = (int)(unsigned)(r0 & 0xffffffffu);
            int ti1 = (int)(unsigned)(r1 & 0xffffffffu);
            float ex0 = __int_as_float((int)(r0 >> 32));
            float ex1 = __int_as_float((int)(r1 >> 32));
            uint2 pk0 = ((const uint2*)(g_tgt_hl + (size_t)ti0 * HID))[lane];
            uint2 pk1 = ((const uint2*)(g_tgt_hl + (size_t)ti1 * HID))[lane];
            denom += ex0 + ex1;
            float2 a0 = __half22float2(*(__half2*)&pk0.x);
            float2 a1 = __half22float2(*(__half2*)&pk0.y);
            float2 b0 = __half22float2(*(__half2*)&pk1.x);
            float2 b1 = __half22float2(*(__half2*)&pk1.y);
            acc.x += ex0 * a0.x + ex1 * b0.x;
            acc.y += ex0 * a0.y + ex1 * b0.y;
            acc.z += ex0 * a1.x + ex1 * b1.x;
            acc.w += ex0 * a1.y + ex1 * b1.y;
        }
        if (p < end) {
            unsigned long long r = g_srec[p];
            int ti = (int)(unsigned)(r & 0xffffffffu);
            float ex = __int_as_float((int)(r >> 32));
            denom += ex;
            uint2 pk = ((const uint2*)(g_tgt_hl + (size_t)ti * HID))[lane];
            float2 f0 = __half22float2(*(__half2*)&pk.x);
            float2 f1 = __half22float2(*(__half2*)&pk.y);
            acc.x += ex * f0.x; acc.y += ex * f0.y;
            acc.z += ex * f1.x; acc.w += ex * f1.y;
        }
        float inv = 1.f / denom;
        float4 bl = ((const float4*)b_lin)[lane];
        res.x += bl.x + acc.x * inv; res.y += bl.y + acc.y * inv;
        res.z += bl.z + acc.z * inv; res.w += bl.w + acc.w * inv;
    }
    ((float4*)(out + (size_t)wid * HID))[lane] = res;
}

// ---------------- launch -----------------------------------------------------------
extern "C" void kernel_launch(void* const* d_in, const int* in_sizes, int n_in,
                              void* d_out, int out_size) {
    const float* source_h   = (const float*)d_in[0];
    const float* target_h   = (const float*)d_in[1];
    const void*  edges      = d_in[2];
    const float* W          = (const float*)d_in[3];
    const float* b_lin      = (const float*)d_in[4];
    const float* att_w      = (const float*)d_in[5];
    const float* att_b      = (const float*)d_in[6];
    const float* bias       = (const float*)d_in[7];

    int nsrc = in_sizes[0] / IN_F;
    int ntgt = in_sizes[1] / IN_F;
    int E    = in_sizes[2] / 2;
    float* out = (float*)d_out;
    int nb = (nsrc + 1023) / 1024;

    setup_kernel<<<129 + (nsrc + 255) / 256, 256>>>(
        W, b_lin, att_w, att_b, (const int*)edges, nsrc);
    hist_kernel<<<(E + 255) / 256, 256>>>(edges, E);
    score_kernel<<<(int)(((long long)nsrc * 32 + 255) / 256), 256>>>(
        source_h, nsrc);
    mma_gemm_kernel<<<(ntgt + 63) / 64, 256>>>(target_h, ntgt);
    scan1_kernel<<<nb, 1024>>>(nsrc);
    scan3_kernel<<<(nsrc + 255) / 256, 256>>>(nsrc, nb);
    scatter_kernel<<<(E + 255) / 256, 256>>>(edges, E);
    agg_kernel<<<(int)(((long long)nsrc * 32 + 255) / 256), 256>>>(
        out, bias, b_lin, nsrc);
}

// round 16
// speedup vs baseline: 1.3394x; 1.0609x over previous
#include <cuda_runtime.h>
#include <cuda_fp16.h>
#include <mma.h>
#include <math.h>
#include <stdint.h>

using namespace nvcuda;

#define NMAX   100000
#define EMAX   1600000
#define IN_F   256
#define HID    128

// ---------------- device scratch (static; no allocations allowed) -------------
// tgt_hl stored fp16 (halves agg gather traffic). Padded by 128 rows: boundary
// GEMM tile stores unguarded into the pad.
__device__ __align__(16) __half g_tgt_hl[(size_t)(NMAX + 128) * HID];
__device__ __align__(16) float g_sscore[NMAX];
__device__ __align__(16) float g_tscore[NMAX];
__device__ __align__(16) unsigned long long g_srec[EMAX];   // packed (ex, ti)
__device__ int g_deg[NMAX];
__device__ int g_base[NMAX];
__device__ int g_cursor[NMAX];
__device__ int g_bsum[128];
__device__ __align__(16) float g_wsproj[IN_F];
__device__ __align__(16) float g_wtproj[IN_F];
__device__ __align__(16) __half g_Wh[HID * IN_F];   // fp16 W (rounded)
__device__ float g_cs;
__device__ float g_ct;
__device__ int   g_idx64;

// ---------------- edge index accessor ------------------------------------------
__device__ __forceinline__ int edge_at(const void* e, int is64, long long pos) {
    if (is64) return (int)((const long long*)e)[pos];
    return ((const int*)e)[pos];
}

// ---------------- fused setup: detect + proj + W fp16 + zero deg ----------------
__global__ void setup_kernel(const float* __restrict__ W,
                             const float* __restrict__ b_lin,
                             const float* __restrict__ att_w,
                             const float* __restrict__ att_b,
                             const int* __restrict__ edges_i32, int nsrc) {
    int b = blockIdx.x, tid = threadIdx.x;
    if (b == 0) {
        float s = 0.f, t = 0.f;
#pragma unroll 8
        for (int h = 0; h < HID; ++h) {
            float w = W[h * IN_F + tid];
            s += w * att_w[h];
            t += w * att_w[HID + h];
        }
        g_wsproj[tid] = s;
        g_wtproj[tid] = t;
        if (tid == 0) {
            float cs = 0.f, ct = 0.f;
            for (int h = 0; h < HID; ++h) {
                cs += b_lin[h] * att_w[h];
                ct += b_lin[h] * att_w[HID + h];
            }
            g_cs = cs;
            g_ct = ct + att_b[0];
        }
        __shared__ int sflag;
        if (tid == 0) sflag = 0;
        __syncthreads();
        if (tid < 128 && edges_i32[2 * tid + 1] != 0) sflag = 1;
        __syncthreads();
        if (tid == 0) g_idx64 = (sflag == 0) ? 1 : 0;
    } else if (b <= 128) {
        int i = (b - 1) * 256 + tid;       // 32768 W elements
        g_Wh[i] = __float2half_rn(W[i]);
    } else {
        int i = (b - 129) * 256 + tid;
        if (i < nsrc) g_deg[i] = 0;
    }
}

// ---------------- fused light pass: source scores | degree histogram -------------
// Both branches are low-register / no-smem, so fusion costs no occupancy.
__global__ void score_hist_kernel(const float* __restrict__ src,
                                  const void* __restrict__ edges,
                                  int nsrc, int E, int nbScore) {
    if (blockIdx.x < nbScore) {
        // warp per node, 8 nodes per block
        int wid = blockIdx.x * 8 + (threadIdx.x >> 5);
        int lane = threadIdx.x & 31;
        if (wid >= nsrc) return;
        const float* row = src + (size_t)wid * IN_F;
        float4 a = ((const float4*)row)[lane];
        float4 b = ((const float4*)row)[lane + 32];
        float4 pa = ((const float4*)g_wsproj)[lane];
        float4 pb = ((const float4*)g_wsproj)[lane + 32];
        float d = a.x * pa.x + a.y * pa.y + a.z * pa.z + a.w * pa.w
                + b.x * pb.x + b.y * pb.y + b.z * pb.z + b.w * pb.w;
#pragma unroll
        for (int o = 16; o; o >>= 1) d += __shfl_down_sync(0xFFFFFFFFu, d, o);
        if (lane == 0) g_sscore[wid] = d + g_cs;
    } else {
        int i = (blockIdx.x - nbScore) * 256 + threadIdx.x;
        if (i < E) {
            int si = edge_at(edges, g_idx64, i);
            atomicAdd(&g_deg[si], 1);
        }
    }
}

// ================= wmma fp16 GEMM + fused t_score ==============================
// g_tgt_hl[M,128] = fp16( A16 @ W16^T ).  BM=64, BN=128, 256 threads (8 warps,
// warp tile 32x32), 3 CTAs/SM target for latency hiding.
#define LDT 40   // padded fp16 row pitch (80 B)

__global__ void __launch_bounds__(256, 3)
mma_gemm_kernel(const float* __restrict__ A, int M) {
    __shared__ __align__(16) char smem_raw[18944];
    __half* sA = (__half*)smem_raw;                   // 64*40*2  = 5120 B
    __half* sW = (__half*)(smem_raw + 5120);          // 128*40*2 = 10240 B

    int tid = threadIdx.x;
    int warp = tid >> 5;
    int lane = tid & 31;
    int wm = warp & 1;        // 2 warp-rows of 32
    int wn = warp >> 1;       // 4 warp-cols of 32
    int row0 = blockIdx.x * 64;

    int rq[2], cq[2], gq[2];
#pragma unroll
    for (int q = 0; q < 2; ++q) {
        int idx = tid + q * 256;          // 0..511
        rq[q] = idx >> 3;                 // 0..63
        cq[q] = (idx & 7) * 4;            // 0..28
        gq[q] = row0 + rq[q];
    }
    int wrq[2], wcq[2];
#pragma unroll
    for (int q = 0; q < 2; ++q) {
        int idx = tid + q * 256;
        wrq[q] = idx >> 2;                // 0..127
        wcq[q] = (idx & 3) * 8;           // 0,8,16,24
    }

    wmma::fragment<wmma::accumulator, 16, 16, 16, float> acc[2][2];
#pragma unroll
    for (int i = 0; i < 2; ++i)
#pragma unroll
        for (int j = 0; j < 2; ++j) wmma::fill_fragment(acc[i][j], 0.f);

    float tsc[2] = {0.f, 0.f};
    float4 pva[2];
    uint4 pw[2];

#pragma unroll
    for (int q = 0; q < 2; ++q) {
        pva[q] = make_float4(0.f, 0.f, 0.f, 0.f);
        if (gq[q] < M) pva[q] = *(const float4*)(A + (size_t)gq[q] * IN_F + cq[q]);
        pw[q] = *(const uint4*)&g_Wh[wrq[q] * IN_F + wcq[q]];
    }

    for (int k0 = 0; k0 < IN_F; k0 += 32) {
#pragma unroll
        for (int q = 0; q < 2; ++q) {
            *(uint4*)&sW[wrq[q] * LDT + wcq[q]] = pw[q];
            float4 v = pva[q];
            int c4 = cq[q];
            tsc[q] += v.x * g_wtproj[k0 + c4]     + v.y * g_wtproj[k0 + c4 + 1]
                    + v.z * g_wtproj[k0 + c4 + 2] + v.w * g_wtproj[k0 + c4 + 3];
            __half2 h01 = __floats2half2_rn(v.x, v.y);
            __half2 h23 = __floats2half2_rn(v.z, v.w);
            *(uint2*)&sA[rq[q] * LDT + c4] =
                make_uint2(*(uint32_t*)&h01, *(uint32_t*)&h23);
        }
        __syncthreads();

        int kn = k0 + 32;
        if (kn < IN_F) {
#pragma unroll
            for (int q = 0; q < 2; ++q) {
                pva[q] = make_float4(0.f, 0.f, 0.f, 0.f);
                if (gq[q] < M)
                    pva[q] = *(const float4*)(A + (size_t)gq[q] * IN_F + kn + cq[q]);
                pw[q] = *(const uint4*)&g_Wh[wrq[q] * IN_F + kn + wcq[q]];
            }
        }

#pragma unroll
        for (int kf = 0; kf < 2; ++kf) {
            wmma::fragment<wmma::matrix_a, 16, 16, 16, __half,
                           wmma::row_major> af[2];
            wmma::fragment<wmma::matrix_b, 16, 16, 16, __half,
                           wmma::col_major> bf[2];
#pragma unroll
            for (int i = 0; i < 2; ++i)
                wmma::load_matrix_sync(af[i],
                    sA + (wm * 32 + i * 16) * LDT + kf * 16, LDT);
#pragma unroll
            for (int j = 0; j < 2; ++j)
                wmma::load_matrix_sync(bf[j],
                    sW + (wn * 32 + j * 16) * LDT + kf * 16, LDT);
#pragma unroll
            for (int i = 0; i < 2; ++i)
#pragma unroll
                for (int j = 0; j < 2; ++j)
                    wmma::mma_sync(acc[i][j], af[i], bf[j], acc[i][j]);
        }
        __syncthreads();
    }

    // t_score reduction: 8 consecutive lanes share one row
#pragma unroll
    for (int q = 0; q < 2; ++q) {
        float d = tsc[q];
        d += __shfl_down_sync(0xFFFFFFFFu, d, 4, 8);
        d += __shfl_down_sync(0xFFFFFFFFu, d, 2, 8);
        d += __shfl_down_sync(0xFFFFFFFFu, d, 1, 8);
        if ((tid & 7) == 0 && gq[q] < M) g_tscore[gq[q]] = d + g_ct;
    }

    // epilogue: acc -> per-warp smem stage -> fp16 global (pad covers overrun)
    float* wscr = (float*)smem_raw + warp * (16 * 36);
#pragma unroll
    for (int i = 0; i < 2; ++i) {
        __syncwarp();
        wmma::store_matrix_sync(wscr, acc[i][0], 36, wmma::mem_row_major);
        wmma::store_matrix_sync(wscr + 16, acc[i][1], 36, wmma::mem_row_major);
        __syncwarp();
        int row = lane & 15, seg = lane >> 4;
        const float* sp = wscr + row * 36 + seg * 16;
        __half2 h[8];
#pragma unroll
        for (int q = 0; q < 8; ++q)
            h[q] = __floats2half2_rn(sp[2 * q], sp[2 * q + 1]);
        size_t grow = (size_t)row0 + wm * 32 + i * 16 + row;
        __half* gp = g_tgt_hl + grow * HID + wn * 32 + seg * 16;
        *(uint4*)gp = *(uint4*)&h[0];
        *(uint4*)(gp + 8) = *(uint4*)&h[4];
    }
}

// ---------------- exclusive scan of degrees (2 kernels) ---------------------------
__global__ void scan1_kernel(int n) {
    __shared__ int s[1024];
    int i = blockIdx.x * 1024 + threadIdx.x;
    int v = (i < n) ? g_deg[i] : 0;
    s[threadIdx.x] = v;
    __syncthreads();
#pragma unroll
    for (int o = 1; o < 1024; o <<= 1) {
        int t = (threadIdx.x >= o) ? s[threadIdx.x - o] : 0;
        __syncthreads();
        s[threadIdx.x] += t;
        __syncthreads();
    }
    if (i < n) g_base[i] = s[threadIdx.x] - v;
    if (threadIdx.x == 1023) g_bsum[blockIdx.x] = s[1023];
}
// scan3 absorbs scan2: every block redundantly prefix-scans the <=128 block
// sums in smem; a 256-thread block covers one (i>>10) group only.
__global__ void scan3_kernel(int n, int nb) {
    __shared__ int s[128];
    int t = threadIdx.x;
    if (t < 128) s[t] = (t < nb) ? g_bsum[t] : 0;
    __syncthreads();
#pragma unroll
    for (int o = 1; o < 128; o <<= 1) {
        int v = (t < 128 && t >= o) ? s[t - o] : 0;
        __syncthreads();
        if (t < 128) s[t] += v;
        __syncthreads();
    }
    int grp = blockIdx.x >> 2;               // constant i>>10 within this block
    int add = (grp == 0) ? 0 : s[grp - 1];   // exclusive prefix
    int i = blockIdx.x * 256 + t;
    if (i < n) {
        int b = g_base[i] + add;
        g_base[i] = b;
        g_cursor[i] = b;
    }
}

// ---------------- scatter: compute ex and write (ex, ti) sorted by si ------------
// e in [-1,1] (tanh): segment-max cancels mathematically in the softmax.
__global__ void scatter_kernel(const void* __restrict__ edges, int E) {
    int i = blockIdx.x * blockDim.x + threadIdx.x;
    if (i >= E) return;
    int is64 = g_idx64;
    int si = edge_at(edges, is64, i);
    int ti = edge_at(edges, is64, (long long)E + i);
    float e = tanhf(g_sscore[si] + g_tscore[ti]);
    float ex = __expf(e);
    int pos = atomicAdd(&g_cursor[si], 1);
    g_srec[pos] = ((unsigned long long)(unsigned)__float_as_int(ex) << 32)
                | (unsigned)ti;
}

// ---------------- aggregate (warp per source node, fp16 rows) ---------------------
// out = (sum ex*v)/(sum ex) + b_lin + bias   (deg>0; else bias only)
__global__ void agg_kernel(float* __restrict__ out,
                           const float* __restrict__ bias,
                           const float* __restrict__ b_lin, int nsrc) {
    int wid = (blockIdx.x * blockDim.x + threadIdx.x) >> 5;
    int lane = threadIdx.x & 31;
    if (wid >= nsrc) return;
    int start = g_base[wid];
    int deg   = g_deg[wid];

    float4 res = ((const float4*)bias)[lane];
    if (deg > 0) {
        float4 acc = make_float4(0.f, 0.f, 0.f, 0.f);
        float denom = 0.f;
        for (int p = start; p < start + deg; ++p) {
            unsigned long long r = g_srec[p];
            int ti = (int)(unsigned)(r & 0xffffffffu);
            float ex = __int_as_float((int)(r >> 32));
            denom += ex;
            uint2 pk = ((const uint2*)(g_tgt_hl + (size_t)ti * HID))[lane];
            float2 f0 = __half22float2(*(__half2*)&pk.x);
            float2 f1 = __half22float2(*(__half2*)&pk.y);
            acc.x += ex * f0.x; acc.y += ex * f0.y;
            acc.z += ex * f1.x; acc.w += ex * f1.y;
        }
        float inv = 1.f / denom;
        float4 bl = ((const float4*)b_lin)[lane];
        res.x += bl.x + acc.x * inv; res.y += bl.y + acc.y * inv;
        res.z += bl.z + acc.z * inv; res.w += bl.w + acc.w * inv;
    }
    ((float4*)(out + (size_t)wid * HID))[lane] = res;
}

// ---------------- launch -----------------------------------------------------------
extern "C" void kernel_launch(void* const* d_in, const int* in_sizes, int n_in,
                              void* d_out, int out_size) {
    const float* source_h   = (const float*)d_in[0];
    const float* target_h   = (const float*)d_in[1];
    const void*  edges      = d_in[2];
    const float* W          = (const float*)d_in[3];
    const float* b_lin      = (const float*)d_in[4];
    const float* att_w      = (const float*)d_in[5];
    const float* att_b      = (const float*)d_in[6];
    const float* bias       = (const float*)d_in[7];

    int nsrc = in_sizes[0] / IN_F;
    int ntgt = in_sizes[1] / IN_F;
    int E    = in_sizes[2] / 2;
    float* out = (float*)d_out;
    int nb = (nsrc + 1023) / 1024;
    int nbScore = (nsrc + 7) / 8;
    int nbHist  = (E + 255) / 256;

    setup_kernel<<<129 + (nsrc + 255) / 256, 256>>>(
        W, b_lin, att_w, att_b, (const int*)edges, nsrc);
    score_hist_kernel<<<nbScore + nbHist, 256>>>(
        source_h, edges, nsrc, E, nbScore);
    mma_gemm_kernel<<<(ntgt + 63) / 64, 256>>>(target_h, ntgt);
    scan1_kernel<<<nb, 1024>>>(nsrc);
    scan3_kernel<<<(nsrc + 255) / 256, 256>>>(nsrc, nb);
    scatter_kernel<<<(E + 255) / 256, 256>>>(edges, E);
    agg_kernel<<<(int)(((long long)nsrc * 32 + 255) / 256), 256>>>(
        out, bias, b_lin, nsrc);
}